// round 12
// baseline (speedup 1.0000x reference)
#include <cuda_runtime.h>
#include <math.h>

#define NIMG 48
#define N    512
#define KF   15
#define BALANCE 0.1f
#define S2C 0.70710678118654752f
#define PI  3.14159265358979323846f
#define ANG (-3.14159265358979323846f)

// Packed spectrum, ROW-MAJOR: g_Z[n*256+rp][slot p] where slot p holds freq
// brev9(p) of Z[rp] = FFT(y[2rp] + i*y[2rp+1]).  50.3 MB, in-place updated.
__device__ __align__(256) float2 g_Z[NIMG * 256 * 512];

// First tile of each Hermitian tile pair (mate(q) = brev6(64 - brev6(q))).
__constant__ int PAIR_A[33] = {0,1,2,4,5,8,9,10,11,16,17,18,19,20,21,22,23,
                               32,33,34,35,36,37,38,39,40,41,42,43,44,45,46,47};

__device__ __forceinline__ int brev6(int x) { return (int)(__brev((unsigned)x) >> 26); }
__device__ __forceinline__ int brev3v(int x) { return ((x & 1) << 2) | (x & 2) | (x >> 2); }
__device__ __forceinline__ float2 cmul(float2 a, float2 b) {
    return make_float2(a.x * b.x - a.y * b.y, a.x * b.y + a.y * b.x);
}
__device__ __forceinline__ float2 cadd(float2 a, float2 b) { return make_float2(a.x + b.x, a.y + b.y); }
__device__ __forceinline__ float2 csub(float2 a, float2 b) { return make_float2(a.x - b.x, a.y - b.y); }
__device__ __forceinline__ float2 wang(float a) { float sn, cs; __sincosf(a, &sn, &cs); return make_float2(cs, sn); }

// ---------------------------------------------------------------------------
// Register radix-8 blocks (3 radix-2 stages).
// ---------------------------------------------------------------------------
template <bool TW>
__device__ __forceinline__ void dif8(float2 v[8], float2 w1) {
    float2 w2, w4;
    if (TW) { w2 = cmul(w1, w1); w4 = cmul(w2, w2); }
    float2 t0 = csub(v[0], v[4]); v[0] = cadd(v[0], v[4]);
    float2 t1 = csub(v[1], v[5]); v[1] = cadd(v[1], v[5]);
    float2 t2 = csub(v[2], v[6]); v[2] = cadd(v[2], v[6]);
    float2 t3 = csub(v[3], v[7]); v[3] = cadd(v[3], v[7]);
    t1 = make_float2(S2C * (t1.x + t1.y), S2C * (t1.y - t1.x));
    t2 = make_float2(t2.y, -t2.x);
    t3 = make_float2(S2C * (t3.y - t3.x), -S2C * (t3.x + t3.y));
    if (TW) { t0 = cmul(t0, w1); t1 = cmul(t1, w1); t2 = cmul(t2, w1); t3 = cmul(t3, w1); }
    v[4] = t0; v[5] = t1; v[6] = t2; v[7] = t3;
    float2 t;
    t = csub(v[0], v[2]); v[0] = cadd(v[0], v[2]); if (TW) t = cmul(t, w2); v[2] = t;
    t = csub(v[1], v[3]); v[1] = cadd(v[1], v[3]); t = make_float2(t.y, -t.x); if (TW) t = cmul(t, w2); v[3] = t;
    t = csub(v[4], v[6]); v[4] = cadd(v[4], v[6]); if (TW) t = cmul(t, w2); v[6] = t;
    t = csub(v[5], v[7]); v[5] = cadd(v[5], v[7]); t = make_float2(t.y, -t.x); if (TW) t = cmul(t, w2); v[7] = t;
    t = csub(v[0], v[1]); v[0] = cadd(v[0], v[1]); if (TW) t = cmul(t, w4); v[1] = t;
    t = csub(v[2], v[3]); v[2] = cadd(v[2], v[3]); if (TW) t = cmul(t, w4); v[3] = t;
    t = csub(v[4], v[5]); v[4] = cadd(v[4], v[5]); if (TW) t = cmul(t, w4); v[5] = t;
    t = csub(v[6], v[7]); v[6] = cadd(v[6], v[7]); if (TW) t = cmul(t, w4); v[7] = t;
}

template <bool TW>
__device__ __forceinline__ void dit8(float2 v[8], float2 w1) {
    float2 w2, w4;
    if (TW) { w2 = cmul(w1, w1); w4 = cmul(w2, w2); }
    float2 t;
    t = v[1]; if (TW) t = cmul(t, w4); v[1] = csub(v[0], t); v[0] = cadd(v[0], t);
    t = v[3]; if (TW) t = cmul(t, w4); v[3] = csub(v[2], t); v[2] = cadd(v[2], t);
    t = v[5]; if (TW) t = cmul(t, w4); v[5] = csub(v[4], t); v[4] = cadd(v[4], t);
    t = v[7]; if (TW) t = cmul(t, w4); v[7] = csub(v[6], t); v[6] = cadd(v[6], t);
    t = v[2]; if (TW) t = cmul(t, w2); v[2] = csub(v[0], t); v[0] = cadd(v[0], t);
    t = v[3]; t = make_float2(-t.y, t.x); if (TW) t = cmul(t, w2); v[3] = csub(v[1], t); v[1] = cadd(v[1], t);
    t = v[6]; if (TW) t = cmul(t, w2); v[6] = csub(v[4], t); v[4] = cadd(v[4], t);
    t = v[7]; t = make_float2(-t.y, t.x); if (TW) t = cmul(t, w2); v[7] = csub(v[5], t); v[5] = cadd(v[5], t);
    t = v[4]; if (TW) t = cmul(t, w1); v[4] = csub(v[0], t); v[0] = cadd(v[0], t);
    t = v[5]; t = make_float2(S2C * (t.x - t.y), S2C * (t.x + t.y)); if (TW) t = cmul(t, w1);
    v[5] = csub(v[1], t); v[1] = cadd(v[1], t);
    t = v[6]; t = make_float2(-t.y, t.x); if (TW) t = cmul(t, w1);
    v[6] = csub(v[2], t); v[2] = cadd(v[2], t);
    t = v[7]; t = make_float2(-S2C * (t.x + t.y), S2C * (t.x - t.y)); if (TW) t = cmul(t, w1);
    v[7] = csub(v[3], t); v[3] = cadd(v[3], t);
}

// Forward 512-pt FFT: v enters x[q+64r], exits slot 8q+r (slot p = freq brev9(p)).
// Linearized padded addressing: PADI(q+64r)=PADI(q)+72r, PADI(64b+q2+8r)=72b+q2+9r,
// PADI(8q+r)=9q+r.
__device__ __forceinline__ void fwd512(float2 v[8], float2* sh, int q) {
    dif8<true>(v, wang(ANG * (float)q / 256.0f));
    float2* p1 = sh + q + (q >> 3);
#pragma unroll
    for (int r = 0; r < 8; r++) p1[72 * r] = v[r];
    __syncthreads();
    float2* p2 = sh + 72 * (q >> 3) + (q & 7);
#pragma unroll
    for (int r = 0; r < 8; r++) v[r] = p2[9 * r];
    dif8<true>(v, wang(ANG * (float)(q & 7) / 32.0f));
#pragma unroll
    for (int r = 0; r < 8; r++) p2[9 * r] = v[r];
    __syncthreads();
    float2* p3 = sh + 9 * q;
#pragma unroll
    for (int r = 0; r < 8; r++) v[r] = p3[r];
    dif8<false>(v, make_float2(1.0f, 0.0f));
}

// ---------------------------------------------------------------------------
// 1) kRowFwdY: 2 real y rows per complex FFT, packed slot-order spectrum
//    stored straight from registers (float4, row-major).
// ---------------------------------------------------------------------------
__global__ void __launch_bounds__(256) kRowFwdY(const float* __restrict__ y) {
    __shared__ float2 sh[4][576];
    int tid = threadIdx.x, q = tid & 63, sub = tid >> 6;
    int g = blockIdx.x * 4 + sub;              // global row-pair id
    int n = g >> 8, rp = g & 255;
    const float* y0 = y + ((size_t)n * N + 2 * rp) * N;
    const float* y1 = y0 + N;
    float2 v[8];
#pragma unroll
    for (int r = 0; r < 8; r++) { int i = q + 64 * r; v[r] = make_float2(y0[i], y1[i]); }
    fwd512(v, sh[sub], q);
    float4* o = reinterpret_cast<float4*>(g_Z + (size_t)g * 512 + 8 * q);
#pragma unroll
    for (int r = 0; r < 4; r++)
        o[r] = make_float4(v[2 * r].x, v[2 * r].y, v[2 * r + 1].x, v[2 * r + 1].y);
}

// ---------------------------------------------------------------------------
// 2) kColHalf: 256 threads handle HALF a Hermitian tile-pair (4 k-columns +
//    their mates via 2D Hermitian symmetry). T synthesis deferred past the
//    forward FFT to keep regs ~64 -> 4 blocks/SM. Linearized addressing.
// ---------------------------------------------------------------------------
__global__ void __launch_bounds__(256, 4) kColHalf(const float* __restrict__ filters) {
    __shared__ float2 sh[2304];          // padded: 512 rows x 4 columns
    __shared__ float2 Gsh[KF * 4];
    __shared__ float ctab[512];
    int tid = threadIdx.x, x = tid & 3, t = tid >> 2;
    ctab[tid]       = 2.0f * __cosf(PI * (float)tid / 256.0f);
    ctab[tid + 256] = 2.0f * __cosf(PI * (float)(tid + 256) / 256.0f);

    int bid = blockIdx.x;
    int n = bid / 66, rem = bid % 66;
    int pi = rem >> 1, half = rem & 1;
    int qa = PAIR_A[pi];
    int c1 = brev6(qa);
    int c2 = (64 - c1) & 63;
    int qb = brev6(c2);
    bool self = (c1 == 0);

    int b = t >> 3, q2 = t & 7;
    int par = t & 1, rp0 = t >> 1;
    int kb6 = brev6(t);

    // Column k this x-lane computes; load/store global slot (tile*8 + slot).
    // par0 holds Z at slot(k), par1 at slot(mate(k)).
    int k, gslot;
    if (!self) {
        k = 64 * brev3v(x) + (half ? c2 : c1);
        int ltile = par ? (half ? qa : qb) : (half ? qb : qa);
        gslot = 8 * ltile + (par ? 7 - x : x);
    } else {                       // self-pair tile 0: k in {0,64,...,256}
        int jj = x + half;         // half0: 0..3, half1: 1..4 (64..192 dup'd)
        k = 64 * jj;
        gslot = par ? brev3v((8 - jj) & 7) : brev3v(jj);
    }

    // Linearized padded smem bases (stride 4 columns, pad 1-per-8 rows):
    float2* e1 = sh + 4 * (t + (t >> 3)) + x;        // + 288*r
    float2* e2 = sh + 288 * b + 4 * q2 + x;          // + 36*r
    float2* e3 = sh + 36 * t + x;                    // + 4*r

    // ---- G_t(k) = sum_c f[t][c] * W^{k(c-7)}  (threads t < 15) ----
    if (t < KF) {
        const float* f = filters + (size_t)(n * KF + t) * KF;
        float2 w1 = wang(ANG * (float)k / 256.0f);
        float2 wp = w1;
        float2 acc = make_float2(f[7], 0.0f);
#pragma unroll
        for (int d = 1; d <= 7; d++) {
            float a = f[7 + d], c = f[7 - d];
            acc.x += (a + c) * wp.x;
            acc.y += (a - c) * wp.y;
            if (d < 7) wp = cmul(wp, w1);
        }
        Gsh[t * 4 + x] = acc;      // synced by the FFT's first barrier below
    }

    // ---- Load packed Z (batched, MLP=8), shfl-exchange with the adjacent-
    //      parity thread (distance 4), Hermitian-unpack to X[u=t+64r, k] ----
    float2* Zc = g_Z + (size_t)n * 256 * 512 + gslot;
    float2 v[8];
#pragma unroll
    for (int r = 0; r < 8; r++) v[r] = Zc[(size_t)(rp0 + 32 * r) * 512];
#pragma unroll
    for (int r = 0; r < 8; r++) {
        float bx = __shfl_xor_sync(0xFFFFFFFFu, v[r].x, 4);
        float by = __shfl_xor_sync(0xFFFFFFFFu, v[r].y, 4);
        float zkx = par ? bx : v[r].x, zky = par ? by : v[r].y;
        float zmx = par ? v[r].x : bx, zmy = par ? v[r].y : by;
        v[r] = par ? make_float2(0.5f * (zky + zmy), 0.5f * (zmx - zkx))
                   : make_float2(0.5f * (zkx + zmx), 0.5f * (zky - zmy));
    }

    // ---- forward column FFT of X ----
    dif8<true>(v, wang(ANG * (float)t / 256.0f));
#pragma unroll
    for (int r = 0; r < 8; r++) e1[288 * r] = v[r];
    __syncthreads();
#pragma unroll
    for (int r = 0; r < 8; r++) v[r] = e2[36 * r];
    dif8<true>(v, wang(ANG * (float)q2 / 32.0f));
#pragma unroll
    for (int r = 0; r < 8; r++) e2[36 * r] = v[r];
    __syncthreads();
#pragma unroll
    for (int r = 0; r < 8; r++) v[r] = e3[4 * r];
    dif8<false>(v, make_float2(1.0f, 0.0f));

    // ---- T column synthesis (deferred; Gsh stable in smem): fold 15 sparse
    //      rows to 8, then 8-pt DFT. T[r] = T(64*brev3(r) + kb6). ----
    float2 T[8];
    {
        int a8 = (kb6 * 8) & 511; if (a8 > 256) a8 -= 512;
        float2 W1 = wang(ANG * (float)kb6 / 256.0f);
        float2 W8 = wang(ANG * (float)a8 / 256.0f);
        float2 wf = W1;
        T[0] = Gsh[7 * 4 + x];
#pragma unroll
        for (int e = 1; e < 8; e++) {
            float2 a  = Gsh[(e + 7) * 4 + x];
            float2 bb = Gsh[(e - 1) * 4 + x];
            float2 wc = make_float2(W8.x * wf.x + W8.y * wf.y,
                                    W8.y * wf.x - W8.x * wf.y);
            T[e] = make_float2(a.x * wf.x - a.y * wf.y + bb.x * wc.x + bb.y * wc.y,
                               a.x * wf.y + a.y * wf.x + bb.y * wc.x - bb.x * wc.y);
            if (e < 7) wf = cmul(wf, W1);
        }
        dif8<false>(T, make_float2(1.0f, 0.0f));
    }

    // ---- Wiener pointwise (slot 8t+r holds row-freq 64*brev3(r)+kb6) ----
    float cj = ctab[k];
#pragma unroll
    for (int r = 0; r < 8; r++) {
        int fr = 64 * brev3v(r) + kb6;
        float reg = 4.0f - ctab[fr] - cj;
        float2 Tv = T[r], Yv = v[r];
        float inv = 1.0f / (Tv.x * Tv.x + Tv.y * Tv.y + BALANCE * reg * reg);
        v[r] = make_float2((Tv.x * Yv.x + Tv.y * Yv.y) * inv,
                           (Tv.x * Yv.y - Tv.y * Yv.x) * inv);
    }

    // ---- inverse column FFT (store1 addrs are thread-private vs fwd load3;
    //      no barrier needed between them) ----
    dit8<false>(v, make_float2(1.0f, 0.0f));
#pragma unroll
    for (int r = 0; r < 8; r++) e3[4 * r] = v[r];
    __syncthreads();
#pragma unroll
    for (int r = 0; r < 8; r++) v[r] = e2[36 * r];
    dit8<true>(v, wang(-ANG * (float)q2 / 32.0f));
#pragma unroll
    for (int r = 0; r < 8; r++) e2[36 * r] = v[r];
    __syncthreads();
#pragma unroll
    for (int r = 0; r < 8; r++) v[r] = e1[288 * r];
    dit8<true>(v, wang(-ANG * (float)t / 256.0f));

    // ---- re-pack: par0 -> P = Xf0 + i*Xf1 at slot(k); par1 -> Q =
    //      conj(Xf0 - i*Xf1) at slot(mate). Store address == load address.
    //      Suppress par1 for self-conjugate columns k = 0, 256. ----
    bool wr = (!par) || (k != 0 && k != 256);
#pragma unroll
    for (int r = 0; r < 8; r++) {
        float bx = __shfl_xor_sync(0xFFFFFFFFu, v[r].x, 4);
        float by = __shfl_xor_sync(0xFFFFFFFFu, v[r].y, 4);
        float2 o = par ? make_float2(bx + v[r].y, v[r].x - by)
                       : make_float2(v[r].x - by, v[r].y + bx);
        if (wr) Zc[(size_t)(rp0 + 32 * r) * 512] = o;
    }
}

// ---------------------------------------------------------------------------
// 3) kRowInv: slot-ordered packed Zf IS the bit-reversed DIT input.
//    Coalesced float4 load -> inverse FFT -> scale+clip -> 2 real rows.
// ---------------------------------------------------------------------------
__global__ void __launch_bounds__(256) kRowInv(float* __restrict__ out) {
    __shared__ float2 sh[4][576];
    int tid = threadIdx.x, q = tid & 63, sub = tid >> 6;
    int g = blockIdx.x * 4 + sub;
    int n = g >> 8, rp = g & 255;
    const float4* ib = reinterpret_cast<const float4*>(g_Z + (size_t)g * 512 + 8 * q);
    float2 v[8];
#pragma unroll
    for (int r = 0; r < 4; r++) {
        float4 L = ib[r];
        v[2 * r]     = make_float2(L.x, L.y);
        v[2 * r + 1] = make_float2(L.z, L.w);
    }
    dit8<false>(v, make_float2(1.0f, 0.0f));
    float2* p3 = sh[sub] + 9 * q;
#pragma unroll
    for (int r = 0; r < 8; r++) p3[r] = v[r];
    __syncthreads();
    float2* p2 = sh[sub] + 72 * (q >> 3) + (q & 7);
#pragma unroll
    for (int r = 0; r < 8; r++) v[r] = p2[9 * r];
    dit8<true>(v, wang(-ANG * (float)(q & 7) / 32.0f));
#pragma unroll
    for (int r = 0; r < 8; r++) p2[9 * r] = v[r];
    __syncthreads();
    float2* p1 = sh[sub] + q + (q >> 3);
#pragma unroll
    for (int r = 0; r < 8; r++) v[r] = p1[72 * r];
    dit8<true>(v, wang(-ANG * (float)q / 256.0f));
    const float sc = 1.0f / (512.0f * 512.0f);
    float* o0 = out + ((size_t)n * N + 2 * rp) * N;
    float* o1 = o0 + N;
#pragma unroll
    for (int r = 0; r < 8; r++) {
        int i = q + 64 * r;
        o0[i] = fminf(1.0f, fmaxf(-1.0f, v[r].x * sc));
        o1[i] = fminf(1.0f, fmaxf(-1.0f, v[r].y * sc));
    }
}

// ---------------------------------------------------------------------------
extern "C" void kernel_launch(void* const* d_in, const int* in_sizes, int n_in,
                              void* d_out, int out_size) {
    const float* y       = (const float*)d_in[0];
    const float* filters = (const float*)d_in[1];
    float* out = (float*)d_out;

    kRowFwdY<<<NIMG * 64, 256>>>(y);          // packed row-major spectrum
    kColHalf<<<NIMG * 66, 256>>>(filters);    // half tile-pair per block
    kRowInv<<<NIMG * 64, 256>>>(out);         // inverse rows from slot order
}

// round 13
// speedup vs baseline: 1.0193x; 1.0193x over previous
#include <cuda_runtime.h>
#include <math.h>

#define NIMG 48
#define N    512
#define KF   15
#define BALANCE 0.1f
#define S2C 0.70710678118654752f
#define PI  3.14159265358979323846f
#define ANG (-3.14159265358979323846f)

// Packed spectrum, ROW-MAJOR: g_Z[n*256+rp][slot p] where slot p holds freq
// brev9(p) of Z[rp] = FFT(y[2rp] + i*y[2rp+1]).  50.3 MB, in-place updated.
__device__ __align__(256) float2 g_Z[NIMG * 256 * 512];

// First tile of each Hermitian tile pair (mate(q) = brev6(64 - brev6(q))).
__constant__ int PAIR_A[33] = {0,1,2,4,5,8,9,10,11,16,17,18,19,20,21,22,23,
                               32,33,34,35,36,37,38,39,40,41,42,43,44,45,46,47};

__device__ __forceinline__ int brev6(int x) { return (int)(__brev((unsigned)x) >> 26); }
__device__ __forceinline__ int brev3v(int x) { return ((x & 1) << 2) | (x & 2) | (x >> 2); }
__device__ __forceinline__ float2 cmul(float2 a, float2 b) {
    return make_float2(a.x * b.x - a.y * b.y, a.x * b.y + a.y * b.x);
}
__device__ __forceinline__ float2 cadd(float2 a, float2 b) { return make_float2(a.x + b.x, a.y + b.y); }
__device__ __forceinline__ float2 csub(float2 a, float2 b) { return make_float2(a.x - b.x, a.y - b.y); }
__device__ __forceinline__ float2 wang(float a) { float sn, cs; __sincosf(a, &sn, &cs); return make_float2(cs, sn); }

// ---------------------------------------------------------------------------
// Register radix-8 blocks (3 radix-2 stages).
// ---------------------------------------------------------------------------
template <bool TW>
__device__ __forceinline__ void dif8(float2 v[8], float2 w1) {
    float2 w2, w4;
    if (TW) { w2 = cmul(w1, w1); w4 = cmul(w2, w2); }
    float2 t0 = csub(v[0], v[4]); v[0] = cadd(v[0], v[4]);
    float2 t1 = csub(v[1], v[5]); v[1] = cadd(v[1], v[5]);
    float2 t2 = csub(v[2], v[6]); v[2] = cadd(v[2], v[6]);
    float2 t3 = csub(v[3], v[7]); v[3] = cadd(v[3], v[7]);
    t1 = make_float2(S2C * (t1.x + t1.y), S2C * (t1.y - t1.x));
    t2 = make_float2(t2.y, -t2.x);
    t3 = make_float2(S2C * (t3.y - t3.x), -S2C * (t3.x + t3.y));
    if (TW) { t0 = cmul(t0, w1); t1 = cmul(t1, w1); t2 = cmul(t2, w1); t3 = cmul(t3, w1); }
    v[4] = t0; v[5] = t1; v[6] = t2; v[7] = t3;
    float2 t;
    t = csub(v[0], v[2]); v[0] = cadd(v[0], v[2]); if (TW) t = cmul(t, w2); v[2] = t;
    t = csub(v[1], v[3]); v[1] = cadd(v[1], v[3]); t = make_float2(t.y, -t.x); if (TW) t = cmul(t, w2); v[3] = t;
    t = csub(v[4], v[6]); v[4] = cadd(v[4], v[6]); if (TW) t = cmul(t, w2); v[6] = t;
    t = csub(v[5], v[7]); v[5] = cadd(v[5], v[7]); t = make_float2(t.y, -t.x); if (TW) t = cmul(t, w2); v[7] = t;
    t = csub(v[0], v[1]); v[0] = cadd(v[0], v[1]); if (TW) t = cmul(t, w4); v[1] = t;
    t = csub(v[2], v[3]); v[2] = cadd(v[2], v[3]); if (TW) t = cmul(t, w4); v[3] = t;
    t = csub(v[4], v[5]); v[4] = cadd(v[4], v[5]); if (TW) t = cmul(t, w4); v[5] = t;
    t = csub(v[6], v[7]); v[6] = cadd(v[6], v[7]); if (TW) t = cmul(t, w4); v[7] = t;
}

template <bool TW>
__device__ __forceinline__ void dit8(float2 v[8], float2 w1) {
    float2 w2, w4;
    if (TW) { w2 = cmul(w1, w1); w4 = cmul(w2, w2); }
    float2 t;
    t = v[1]; if (TW) t = cmul(t, w4); v[1] = csub(v[0], t); v[0] = cadd(v[0], t);
    t = v[3]; if (TW) t = cmul(t, w4); v[3] = csub(v[2], t); v[2] = cadd(v[2], t);
    t = v[5]; if (TW) t = cmul(t, w4); v[5] = csub(v[4], t); v[4] = cadd(v[4], t);
    t = v[7]; if (TW) t = cmul(t, w4); v[7] = csub(v[6], t); v[6] = cadd(v[6], t);
    t = v[2]; if (TW) t = cmul(t, w2); v[2] = csub(v[0], t); v[0] = cadd(v[0], t);
    t = v[3]; t = make_float2(-t.y, t.x); if (TW) t = cmul(t, w2); v[3] = csub(v[1], t); v[1] = cadd(v[1], t);
    t = v[6]; if (TW) t = cmul(t, w2); v[6] = csub(v[4], t); v[4] = cadd(v[4], t);
    t = v[7]; t = make_float2(-t.y, t.x); if (TW) t = cmul(t, w2); v[7] = csub(v[5], t); v[5] = cadd(v[5], t);
    t = v[4]; if (TW) t = cmul(t, w1); v[4] = csub(v[0], t); v[0] = cadd(v[0], t);
    t = v[5]; t = make_float2(S2C * (t.x - t.y), S2C * (t.x + t.y)); if (TW) t = cmul(t, w1);
    v[5] = csub(v[1], t); v[1] = cadd(v[1], t);
    t = v[6]; t = make_float2(-t.y, t.x); if (TW) t = cmul(t, w1);
    v[6] = csub(v[2], t); v[2] = cadd(v[2], t);
    t = v[7]; t = make_float2(-S2C * (t.x + t.y), S2C * (t.x - t.y)); if (TW) t = cmul(t, w1);
    v[7] = csub(v[3], t); v[3] = cadd(v[3], t);
}

// Forward 512-pt FFT: v enters x[q+64r], exits slot 8q+r (slot p = freq brev9(p)).
// Linearized padded addressing. Exchange 2 is intra-warp (b-group region
// [72b,72b+72) owned by q in [8b,8b+8) = 8 consecutive lanes) -> __syncwarp.
__device__ __forceinline__ void fwd512(float2 v[8], float2* sh, int q) {
    dif8<true>(v, wang(ANG * (float)q / 256.0f));
    float2* p1 = sh + q + (q >> 3);
#pragma unroll
    for (int r = 0; r < 8; r++) p1[72 * r] = v[r];
    __syncthreads();
    float2* p2 = sh + 72 * (q >> 3) + (q & 7);
#pragma unroll
    for (int r = 0; r < 8; r++) v[r] = p2[9 * r];
    dif8<true>(v, wang(ANG * (float)(q & 7) / 32.0f));
#pragma unroll
    for (int r = 0; r < 8; r++) p2[9 * r] = v[r];
    __syncwarp();
    float2* p3 = sh + 9 * q;
#pragma unroll
    for (int r = 0; r < 8; r++) v[r] = p3[r];
    dif8<false>(v, make_float2(1.0f, 0.0f));
}

// ---------------------------------------------------------------------------
// 1) kRowFwdY: 2 real y rows per complex FFT, packed slot-order spectrum
//    stored straight from registers (float4, row-major).
// ---------------------------------------------------------------------------
__global__ void __launch_bounds__(256) kRowFwdY(const float* __restrict__ y) {
    __shared__ float2 sh[4][576];
    int tid = threadIdx.x, q = tid & 63, sub = tid >> 6;
    int g = blockIdx.x * 4 + sub;              // global row-pair id
    int n = g >> 8, rp = g & 255;
    const float* y0 = y + ((size_t)n * N + 2 * rp) * N;
    const float* y1 = y0 + N;
    float2 v[8];
#pragma unroll
    for (int r = 0; r < 8; r++) { int i = q + 64 * r; v[r] = make_float2(y0[i], y1[i]); }
    fwd512(v, sh[sub], q);
    float4* o = reinterpret_cast<float4*>(g_Z + (size_t)g * 512 + 8 * q);
#pragma unroll
    for (int r = 0; r < 4; r++)
        o[r] = make_float4(v[2 * r].x, v[2 * r].y, v[2 * r + 1].x, v[2 * r + 1].y);
}

// ---------------------------------------------------------------------------
// 2) kColHalf: 256 threads handle HALF a Hermitian tile-pair (4 k-columns +
//    their mates via 2D Hermitian symmetry). T synthesis deferred past the
//    forward FFT to keep regs ~64 -> 4 blocks/SM. Intra-warp exchanges use
//    __syncwarp (b-group rows [64b,64b+64) x 4 cols = tids [32b,32b+32)).
// ---------------------------------------------------------------------------
__global__ void __launch_bounds__(256, 4) kColHalf(const float* __restrict__ filters) {
    __shared__ float2 sh[2304];          // padded: 512 rows x 4 columns
    __shared__ float2 Gsh[KF * 4];
    __shared__ float ctab[512];
    int tid = threadIdx.x, x = tid & 3, t = tid >> 2;
    ctab[tid]       = 2.0f * __cosf(PI * (float)tid / 256.0f);
    ctab[tid + 256] = 2.0f * __cosf(PI * (float)(tid + 256) / 256.0f);

    int bid = blockIdx.x;
    int n = bid / 66, rem = bid % 66;
    int pi = rem >> 1, half = rem & 1;
    int qa = PAIR_A[pi];
    int c1 = brev6(qa);
    int c2 = (64 - c1) & 63;
    int qb = brev6(c2);
    bool self = (c1 == 0);

    int b = t >> 3, q2 = t & 7;
    int par = t & 1, rp0 = t >> 1;
    int kb6 = brev6(t);

    // Column k this x-lane computes; load/store global slot (tile*8 + slot).
    // par0 holds Z at slot(k), par1 at slot(mate(k)).
    int k, gslot;
    if (!self) {
        k = 64 * brev3v(x) + (half ? c2 : c1);
        int ltile = par ? (half ? qa : qb) : (half ? qb : qa);
        gslot = 8 * ltile + (par ? 7 - x : x);
    } else {                       // self-pair tile 0: k in {0,64,...,256}
        int jj = x + half;         // half0: 0..3, half1: 1..4 (64..192 dup'd)
        k = 64 * jj;
        gslot = par ? brev3v((8 - jj) & 7) : brev3v(jj);
    }

    // Linearized padded smem bases (stride 4 columns, pad 1-per-8 rows):
    float2* e1 = sh + 4 * (t + (t >> 3)) + x;        // + 288*r
    float2* e2 = sh + 288 * b + 4 * q2 + x;          // + 36*r
    float2* e3 = sh + 36 * t + x;                    // + 4*r

    // ---- G_t(k) = sum_c f[t][c] * W^{k(c-7)}  (threads t < 15) ----
    if (t < KF) {
        const float* f = filters + (size_t)(n * KF + t) * KF;
        float2 w1 = wang(ANG * (float)k / 256.0f);
        float2 wp = w1;
        float2 acc = make_float2(f[7], 0.0f);
#pragma unroll
        for (int d = 1; d <= 7; d++) {
            float a = f[7 + d], c = f[7 - d];
            acc.x += (a + c) * wp.x;
            acc.y += (a - c) * wp.y;
            if (d < 7) wp = cmul(wp, w1);
        }
        Gsh[t * 4 + x] = acc;      // synced by the FFT's first barrier below
    }

    // ---- Load packed Z (batched, MLP=8), shfl-exchange with the adjacent-
    //      parity thread (distance 4), Hermitian-unpack to X[u=t+64r, k] ----
    float2* Zc = g_Z + (size_t)n * 256 * 512 + gslot;
    float2 v[8];
#pragma unroll
    for (int r = 0; r < 8; r++) v[r] = Zc[(size_t)(rp0 + 32 * r) * 512];
#pragma unroll
    for (int r = 0; r < 8; r++) {
        float bx = __shfl_xor_sync(0xFFFFFFFFu, v[r].x, 4);
        float by = __shfl_xor_sync(0xFFFFFFFFu, v[r].y, 4);
        float zkx = par ? bx : v[r].x, zky = par ? by : v[r].y;
        float zmx = par ? v[r].x : bx, zmy = par ? v[r].y : by;
        v[r] = par ? make_float2(0.5f * (zky + zmy), 0.5f * (zmx - zkx))
                   : make_float2(0.5f * (zkx + zmx), 0.5f * (zky - zmy));
    }

    // ---- forward column FFT of X ----
    dif8<true>(v, wang(ANG * (float)t / 256.0f));
#pragma unroll
    for (int r = 0; r < 8; r++) e1[288 * r] = v[r];
    __syncthreads();
#pragma unroll
    for (int r = 0; r < 8; r++) v[r] = e2[36 * r];
    dif8<true>(v, wang(ANG * (float)q2 / 32.0f));
#pragma unroll
    for (int r = 0; r < 8; r++) e2[36 * r] = v[r];
    __syncwarp();
#pragma unroll
    for (int r = 0; r < 8; r++) v[r] = e3[4 * r];
    dif8<false>(v, make_float2(1.0f, 0.0f));

    // ---- T column synthesis (deferred; Gsh stable in smem): fold 15 sparse
    //      rows to 8, then 8-pt DFT. T[r] = T(64*brev3(r) + kb6). ----
    float2 T[8];
    {
        int a8 = (kb6 * 8) & 511; if (a8 > 256) a8 -= 512;
        float2 W1 = wang(ANG * (float)kb6 / 256.0f);
        float2 W8 = wang(ANG * (float)a8 / 256.0f);
        float2 wf = W1;
        T[0] = Gsh[7 * 4 + x];
#pragma unroll
        for (int e = 1; e < 8; e++) {
            float2 a  = Gsh[(e + 7) * 4 + x];
            float2 bb = Gsh[(e - 1) * 4 + x];
            float2 wc = make_float2(W8.x * wf.x + W8.y * wf.y,
                                    W8.y * wf.x - W8.x * wf.y);
            T[e] = make_float2(a.x * wf.x - a.y * wf.y + bb.x * wc.x + bb.y * wc.y,
                               a.x * wf.y + a.y * wf.x + bb.y * wc.x - bb.x * wc.y);
            if (e < 7) wf = cmul(wf, W1);
        }
        dif8<false>(T, make_float2(1.0f, 0.0f));
    }

    // ---- Wiener pointwise (slot 8t+r holds row-freq 64*brev3(r)+kb6) ----
    float cj = ctab[k];
#pragma unroll
    for (int r = 0; r < 8; r++) {
        int fr = 64 * brev3v(r) + kb6;
        float reg = 4.0f - ctab[fr] - cj;
        float2 Tv = T[r], Yv = v[r];
        float inv = 1.0f / (Tv.x * Tv.x + Tv.y * Tv.y + BALANCE * reg * reg);
        v[r] = make_float2((Tv.x * Yv.x + Tv.y * Yv.y) * inv,
                           (Tv.x * Yv.y - Tv.y * Yv.x) * inv);
    }

    // ---- inverse column FFT (store e3 addrs are thread-private vs fwd load
    //      e3; the e3 -> e2 exchange is intra-warp) ----
    dit8<false>(v, make_float2(1.0f, 0.0f));
#pragma unroll
    for (int r = 0; r < 8; r++) e3[4 * r] = v[r];
    __syncwarp();
#pragma unroll
    for (int r = 0; r < 8; r++) v[r] = e2[36 * r];
    dit8<true>(v, wang(-ANG * (float)q2 / 32.0f));
#pragma unroll
    for (int r = 0; r < 8; r++) e2[36 * r] = v[r];
    __syncthreads();
#pragma unroll
    for (int r = 0; r < 8; r++) v[r] = e1[288 * r];
    dit8<true>(v, wang(-ANG * (float)t / 256.0f));

    // ---- re-pack: par0 -> P = Xf0 + i*Xf1 at slot(k); par1 -> Q =
    //      conj(Xf0 - i*Xf1) at slot(mate). Store address == load address.
    //      Suppress par1 for self-conjugate columns k = 0, 256. ----
    bool wr = (!par) || (k != 0 && k != 256);
#pragma unroll
    for (int r = 0; r < 8; r++) {
        float bx = __shfl_xor_sync(0xFFFFFFFFu, v[r].x, 4);
        float by = __shfl_xor_sync(0xFFFFFFFFu, v[r].y, 4);
        float2 o = par ? make_float2(bx + v[r].y, v[r].x - by)
                       : make_float2(v[r].x - by, v[r].y + bx);
        if (wr) Zc[(size_t)(rp0 + 32 * r) * 512] = o;
    }
}

// ---------------------------------------------------------------------------
// 3) kRowInv: slot-ordered packed Zf IS the bit-reversed DIT input.
//    Coalesced float4 load -> inverse FFT -> scale+clip -> 2 real rows.
//    First exchange (p3 -> p2) is intra-warp -> __syncwarp.
// ---------------------------------------------------------------------------
__global__ void __launch_bounds__(256) kRowInv(float* __restrict__ out) {
    __shared__ float2 sh[4][576];
    int tid = threadIdx.x, q = tid & 63, sub = tid >> 6;
    int g = blockIdx.x * 4 + sub;
    int n = g >> 8, rp = g & 255;
    const float4* ib = reinterpret_cast<const float4*>(g_Z + (size_t)g * 512 + 8 * q);
    float2 v[8];
#pragma unroll
    for (int r = 0; r < 4; r++) {
        float4 L = ib[r];
        v[2 * r]     = make_float2(L.x, L.y);
        v[2 * r + 1] = make_float2(L.z, L.w);
    }
    dit8<false>(v, make_float2(1.0f, 0.0f));
    float2* p3 = sh[sub] + 9 * q;
#pragma unroll
    for (int r = 0; r < 8; r++) p3[r] = v[r];
    __syncwarp();
    float2* p2 = sh[sub] + 72 * (q >> 3) + (q & 7);
#pragma unroll
    for (int r = 0; r < 8; r++) v[r] = p2[9 * r];
    dit8<true>(v, wang(-ANG * (float)(q & 7) / 32.0f));
#pragma unroll
    for (int r = 0; r < 8; r++) p2[9 * r] = v[r];
    __syncthreads();
    float2* p1 = sh[sub] + q + (q >> 3);
#pragma unroll
    for (int r = 0; r < 8; r++) v[r] = p1[72 * r];
    dit8<true>(v, wang(-ANG * (float)q / 256.0f));
    const float sc = 1.0f / (512.0f * 512.0f);
    float* o0 = out + ((size_t)n * N + 2 * rp) * N;
    float* o1 = o0 + N;
#pragma unroll
    for (int r = 0; r < 8; r++) {
        int i = q + 64 * r;
        o0[i] = fminf(1.0f, fmaxf(-1.0f, v[r].x * sc));
        o1[i] = fminf(1.0f, fmaxf(-1.0f, v[r].y * sc));
    }
}

// ---------------------------------------------------------------------------
extern "C" void kernel_launch(void* const* d_in, const int* in_sizes, int n_in,
                              void* d_out, int out_size) {
    const float* y       = (const float*)d_in[0];
    const float* filters = (const float*)d_in[1];
    float* out = (float*)d_out;

    kRowFwdY<<<NIMG * 64, 256>>>(y);          // packed row-major spectrum
    kColHalf<<<NIMG * 66, 256>>>(filters);    // half tile-pair per block
    kRowInv<<<NIMG * 64, 256>>>(out);         // inverse rows from slot order
}

// round 14
// speedup vs baseline: 1.0944x; 1.0736x over previous
#include <cuda_runtime.h>
#include <math.h>

#define NIMG 48
#define N    512
#define KF   15
#define BALANCE 0.1f
#define S2C 0.70710678118654752f
#define PI  3.14159265358979323846f
#define ANG (-3.14159265358979323846f)
#define NCHAIN 3
#define IMGS_PER_CHAIN (NIMG / NCHAIN)

// Packed spectrum, ROW-MAJOR: g_Z[n*256+rp][slot p] where slot p holds freq
// brev9(p) of Z[rp] = FFT(y[2rp] + i*y[2rp+1]).  50.3 MB, in-place updated.
__device__ __align__(256) float2 g_Z[NIMG * 256 * 512];

// First tile of each Hermitian tile pair (mate(q) = brev6(64 - brev6(q))).
__constant__ int PAIR_A[33] = {0,1,2,4,5,8,9,10,11,16,17,18,19,20,21,22,23,
                               32,33,34,35,36,37,38,39,40,41,42,43,44,45,46,47};

__device__ __forceinline__ int brev6(int x) { return (int)(__brev((unsigned)x) >> 26); }
__device__ __forceinline__ int brev3v(int x) { return ((x & 1) << 2) | (x & 2) | (x >> 2); }
__device__ __forceinline__ float2 cmul(float2 a, float2 b) {
    return make_float2(a.x * b.x - a.y * b.y, a.x * b.y + a.y * b.x);
}
__device__ __forceinline__ float2 cadd(float2 a, float2 b) { return make_float2(a.x + b.x, a.y + b.y); }
__device__ __forceinline__ float2 csub(float2 a, float2 b) { return make_float2(a.x - b.x, a.y - b.y); }
__device__ __forceinline__ float2 wang(float a) { float sn, cs; __sincosf(a, &sn, &cs); return make_float2(cs, sn); }

// ---------------------------------------------------------------------------
// Register radix-8 blocks (3 radix-2 stages).
// ---------------------------------------------------------------------------
template <bool TW>
__device__ __forceinline__ void dif8(float2 v[8], float2 w1) {
    float2 w2, w4;
    if (TW) { w2 = cmul(w1, w1); w4 = cmul(w2, w2); }
    float2 t0 = csub(v[0], v[4]); v[0] = cadd(v[0], v[4]);
    float2 t1 = csub(v[1], v[5]); v[1] = cadd(v[1], v[5]);
    float2 t2 = csub(v[2], v[6]); v[2] = cadd(v[2], v[6]);
    float2 t3 = csub(v[3], v[7]); v[3] = cadd(v[3], v[7]);
    t1 = make_float2(S2C * (t1.x + t1.y), S2C * (t1.y - t1.x));
    t2 = make_float2(t2.y, -t2.x);
    t3 = make_float2(S2C * (t3.y - t3.x), -S2C * (t3.x + t3.y));
    if (TW) { t0 = cmul(t0, w1); t1 = cmul(t1, w1); t2 = cmul(t2, w1); t3 = cmul(t3, w1); }
    v[4] = t0; v[5] = t1; v[6] = t2; v[7] = t3;
    float2 t;
    t = csub(v[0], v[2]); v[0] = cadd(v[0], v[2]); if (TW) t = cmul(t, w2); v[2] = t;
    t = csub(v[1], v[3]); v[1] = cadd(v[1], v[3]); t = make_float2(t.y, -t.x); if (TW) t = cmul(t, w2); v[3] = t;
    t = csub(v[4], v[6]); v[4] = cadd(v[4], v[6]); if (TW) t = cmul(t, w2); v[6] = t;
    t = csub(v[5], v[7]); v[5] = cadd(v[5], v[7]); t = make_float2(t.y, -t.x); if (TW) t = cmul(t, w2); v[7] = t;
    t = csub(v[0], v[1]); v[0] = cadd(v[0], v[1]); if (TW) t = cmul(t, w4); v[1] = t;
    t = csub(v[2], v[3]); v[2] = cadd(v[2], v[3]); if (TW) t = cmul(t, w4); v[3] = t;
    t = csub(v[4], v[5]); v[4] = cadd(v[4], v[5]); if (TW) t = cmul(t, w4); v[5] = t;
    t = csub(v[6], v[7]); v[6] = cadd(v[6], v[7]); if (TW) t = cmul(t, w4); v[7] = t;
}

template <bool TW>
__device__ __forceinline__ void dit8(float2 v[8], float2 w1) {
    float2 w2, w4;
    if (TW) { w2 = cmul(w1, w1); w4 = cmul(w2, w2); }
    float2 t;
    t = v[1]; if (TW) t = cmul(t, w4); v[1] = csub(v[0], t); v[0] = cadd(v[0], t);
    t = v[3]; if (TW) t = cmul(t, w4); v[3] = csub(v[2], t); v[2] = cadd(v[2], t);
    t = v[5]; if (TW) t = cmul(t, w4); v[5] = csub(v[4], t); v[4] = cadd(v[4], t);
    t = v[7]; if (TW) t = cmul(t, w4); v[7] = csub(v[6], t); v[6] = cadd(v[6], t);
    t = v[2]; if (TW) t = cmul(t, w2); v[2] = csub(v[0], t); v[0] = cadd(v[0], t);
    t = v[3]; t = make_float2(-t.y, t.x); if (TW) t = cmul(t, w2); v[3] = csub(v[1], t); v[1] = cadd(v[1], t);
    t = v[6]; if (TW) t = cmul(t, w2); v[6] = csub(v[4], t); v[4] = cadd(v[4], t);
    t = v[7]; t = make_float2(-t.y, t.x); if (TW) t = cmul(t, w2); v[7] = csub(v[5], t); v[5] = cadd(v[5], t);
    t = v[4]; if (TW) t = cmul(t, w1); v[4] = csub(v[0], t); v[0] = cadd(v[0], t);
    t = v[5]; t = make_float2(S2C * (t.x - t.y), S2C * (t.x + t.y)); if (TW) t = cmul(t, w1);
    v[5] = csub(v[1], t); v[1] = cadd(v[1], t);
    t = v[6]; t = make_float2(-t.y, t.x); if (TW) t = cmul(t, w1);
    v[6] = csub(v[2], t); v[2] = cadd(v[2], t);
    t = v[7]; t = make_float2(-S2C * (t.x + t.y), S2C * (t.x - t.y)); if (TW) t = cmul(t, w1);
    v[7] = csub(v[3], t); v[3] = cadd(v[3], t);
}

// Forward 512-pt FFT: v enters x[q+64r], exits slot 8q+r (slot p = freq brev9(p)).
// Linearized padded addressing. Exchange 2 is intra-warp -> __syncwarp.
__device__ __forceinline__ void fwd512(float2 v[8], float2* sh, int q) {
    dif8<true>(v, wang(ANG * (float)q / 256.0f));
    float2* p1 = sh + q + (q >> 3);
#pragma unroll
    for (int r = 0; r < 8; r++) p1[72 * r] = v[r];
    __syncthreads();
    float2* p2 = sh + 72 * (q >> 3) + (q & 7);
#pragma unroll
    for (int r = 0; r < 8; r++) v[r] = p2[9 * r];
    dif8<true>(v, wang(ANG * (float)(q & 7) / 32.0f));
#pragma unroll
    for (int r = 0; r < 8; r++) p2[9 * r] = v[r];
    __syncwarp();
    float2* p3 = sh + 9 * q;
#pragma unroll
    for (int r = 0; r < 8; r++) v[r] = p3[r];
    dif8<false>(v, make_float2(1.0f, 0.0f));
}

// ---------------------------------------------------------------------------
// 1) kRowFwdY: 2 real y rows per complex FFT, packed slot-order spectrum.
//    n0 = image offset of this chain.
// ---------------------------------------------------------------------------
__global__ void __launch_bounds__(256) kRowFwdY(const float* __restrict__ y, int n0) {
    __shared__ float2 sh[4][576];
    int tid = threadIdx.x, q = tid & 63, sub = tid >> 6;
    int g = blockIdx.x * 4 + sub;              // chain-local row-pair id
    int n = (g >> 8) + n0, rp = g & 255;
    const float* y0 = y + ((size_t)n * N + 2 * rp) * N;
    const float* y1 = y0 + N;
    float2 v[8];
#pragma unroll
    for (int r = 0; r < 8; r++) { int i = q + 64 * r; v[r] = make_float2(y0[i], y1[i]); }
    fwd512(v, sh[sub], q);
    float4* o = reinterpret_cast<float4*>(g_Z + ((size_t)n * 256 + rp) * 512 + 8 * q);
#pragma unroll
    for (int r = 0; r < 4; r++)
        o[r] = make_float4(v[2 * r].x, v[2 * r].y, v[2 * r + 1].x, v[2 * r + 1].y);
}

// ---------------------------------------------------------------------------
// 2) kColHalf: 256 threads handle HALF a Hermitian tile-pair (4 k-columns +
//    their mates). T synthesis deferred past the forward FFT (regs ~64).
// ---------------------------------------------------------------------------
__global__ void __launch_bounds__(256, 4) kColHalf(const float* __restrict__ filters, int n0) {
    __shared__ float2 sh[2304];          // padded: 512 rows x 4 columns
    __shared__ float2 Gsh[KF * 4];
    __shared__ float ctab[512];
    int tid = threadIdx.x, x = tid & 3, t = tid >> 2;
    ctab[tid]       = 2.0f * __cosf(PI * (float)tid / 256.0f);
    ctab[tid + 256] = 2.0f * __cosf(PI * (float)(tid + 256) / 256.0f);

    int bid = blockIdx.x;
    int n = bid / 66 + n0, rem = bid % 66;
    int pi = rem >> 1, half = rem & 1;
    int qa = PAIR_A[pi];
    int c1 = brev6(qa);
    int c2 = (64 - c1) & 63;
    int qb = brev6(c2);
    bool self = (c1 == 0);

    int b = t >> 3, q2 = t & 7;
    int par = t & 1, rp0 = t >> 1;
    int kb6 = brev6(t);

    int k, gslot;
    if (!self) {
        k = 64 * brev3v(x) + (half ? c2 : c1);
        int ltile = par ? (half ? qa : qb) : (half ? qb : qa);
        gslot = 8 * ltile + (par ? 7 - x : x);
    } else {                       // self-pair tile 0: k in {0,64,...,256}
        int jj = x + half;         // half0: 0..3, half1: 1..4 (64..192 dup'd)
        k = 64 * jj;
        gslot = par ? brev3v((8 - jj) & 7) : brev3v(jj);
    }

    float2* e1 = sh + 4 * (t + (t >> 3)) + x;        // + 288*r
    float2* e2 = sh + 288 * b + 4 * q2 + x;          // + 36*r
    float2* e3 = sh + 36 * t + x;                    // + 4*r

    // ---- G_t(k) = sum_c f[t][c] * W^{k(c-7)}  (threads t < 15) ----
    if (t < KF) {
        const float* f = filters + (size_t)(n * KF + t) * KF;
        float2 w1 = wang(ANG * (float)k / 256.0f);
        float2 wp = w1;
        float2 acc = make_float2(f[7], 0.0f);
#pragma unroll
        for (int d = 1; d <= 7; d++) {
            float a = f[7 + d], c = f[7 - d];
            acc.x += (a + c) * wp.x;
            acc.y += (a - c) * wp.y;
            if (d < 7) wp = cmul(wp, w1);
        }
        Gsh[t * 4 + x] = acc;      // synced by the FFT's first barrier below
    }

    // ---- Load packed Z, shfl-exchange (distance 4), Hermitian unpack ----
    float2* Zc = g_Z + (size_t)n * 256 * 512 + gslot;
    float2 v[8];
#pragma unroll
    for (int r = 0; r < 8; r++) v[r] = Zc[(size_t)(rp0 + 32 * r) * 512];
#pragma unroll
    for (int r = 0; r < 8; r++) {
        float bx = __shfl_xor_sync(0xFFFFFFFFu, v[r].x, 4);
        float by = __shfl_xor_sync(0xFFFFFFFFu, v[r].y, 4);
        float zkx = par ? bx : v[r].x, zky = par ? by : v[r].y;
        float zmx = par ? v[r].x : bx, zmy = par ? v[r].y : by;
        v[r] = par ? make_float2(0.5f * (zky + zmy), 0.5f * (zmx - zkx))
                   : make_float2(0.5f * (zkx + zmx), 0.5f * (zky - zmy));
    }

    // ---- forward column FFT of X ----
    dif8<true>(v, wang(ANG * (float)t / 256.0f));
#pragma unroll
    for (int r = 0; r < 8; r++) e1[288 * r] = v[r];
    __syncthreads();
#pragma unroll
    for (int r = 0; r < 8; r++) v[r] = e2[36 * r];
    dif8<true>(v, wang(ANG * (float)q2 / 32.0f));
#pragma unroll
    for (int r = 0; r < 8; r++) e2[36 * r] = v[r];
    __syncwarp();
#pragma unroll
    for (int r = 0; r < 8; r++) v[r] = e3[4 * r];
    dif8<false>(v, make_float2(1.0f, 0.0f));

    // ---- T column synthesis: fold 15 sparse rows to 8, then 8-pt DFT ----
    float2 T[8];
    {
        int a8 = (kb6 * 8) & 511; if (a8 > 256) a8 -= 512;
        float2 W1 = wang(ANG * (float)kb6 / 256.0f);
        float2 W8 = wang(ANG * (float)a8 / 256.0f);
        float2 wf = W1;
        T[0] = Gsh[7 * 4 + x];
#pragma unroll
        for (int e = 1; e < 8; e++) {
            float2 a  = Gsh[(e + 7) * 4 + x];
            float2 bb = Gsh[(e - 1) * 4 + x];
            float2 wc = make_float2(W8.x * wf.x + W8.y * wf.y,
                                    W8.y * wf.x - W8.x * wf.y);
            T[e] = make_float2(a.x * wf.x - a.y * wf.y + bb.x * wc.x + bb.y * wc.y,
                               a.x * wf.y + a.y * wf.x + bb.y * wc.x - bb.x * wc.y);
            if (e < 7) wf = cmul(wf, W1);
        }
        dif8<false>(T, make_float2(1.0f, 0.0f));
    }

    // ---- Wiener pointwise (slot 8t+r holds row-freq 64*brev3(r)+kb6) ----
    float cj = ctab[k];
#pragma unroll
    for (int r = 0; r < 8; r++) {
        int fr = 64 * brev3v(r) + kb6;
        float reg = 4.0f - ctab[fr] - cj;
        float2 Tv = T[r], Yv = v[r];
        float inv = 1.0f / (Tv.x * Tv.x + Tv.y * Tv.y + BALANCE * reg * reg);
        v[r] = make_float2((Tv.x * Yv.x + Tv.y * Yv.y) * inv,
                           (Tv.x * Yv.y - Tv.y * Yv.x) * inv);
    }

    // ---- inverse column FFT ----
    dit8<false>(v, make_float2(1.0f, 0.0f));
#pragma unroll
    for (int r = 0; r < 8; r++) e3[4 * r] = v[r];
    __syncwarp();
#pragma unroll
    for (int r = 0; r < 8; r++) v[r] = e2[36 * r];
    dit8<true>(v, wang(-ANG * (float)q2 / 32.0f));
#pragma unroll
    for (int r = 0; r < 8; r++) e2[36 * r] = v[r];
    __syncthreads();
#pragma unroll
    for (int r = 0; r < 8; r++) v[r] = e1[288 * r];
    dit8<true>(v, wang(-ANG * (float)t / 256.0f));

    // ---- re-pack; suppress par1 for self-conjugate columns k = 0, 256 ----
    bool wr = (!par) || (k != 0 && k != 256);
#pragma unroll
    for (int r = 0; r < 8; r++) {
        float bx = __shfl_xor_sync(0xFFFFFFFFu, v[r].x, 4);
        float by = __shfl_xor_sync(0xFFFFFFFFu, v[r].y, 4);
        float2 o = par ? make_float2(bx + v[r].y, v[r].x - by)
                       : make_float2(v[r].x - by, v[r].y + bx);
        if (wr) Zc[(size_t)(rp0 + 32 * r) * 512] = o;
    }
}

// ---------------------------------------------------------------------------
// 3) kRowInv: slot-ordered packed Zf IS the bit-reversed DIT input.
// ---------------------------------------------------------------------------
__global__ void __launch_bounds__(256) kRowInv(float* __restrict__ out, int n0) {
    __shared__ float2 sh[4][576];
    int tid = threadIdx.x, q = tid & 63, sub = tid >> 6;
    int g = blockIdx.x * 4 + sub;
    int n = (g >> 8) + n0, rp = g & 255;
    const float4* ib = reinterpret_cast<const float4*>(
        g_Z + ((size_t)n * 256 + rp) * 512 + 8 * q);
    float2 v[8];
#pragma unroll
    for (int r = 0; r < 4; r++) {
        float4 L = ib[r];
        v[2 * r]     = make_float2(L.x, L.y);
        v[2 * r + 1] = make_float2(L.z, L.w);
    }
    dit8<false>(v, make_float2(1.0f, 0.0f));
    float2* p3 = sh[sub] + 9 * q;
#pragma unroll
    for (int r = 0; r < 8; r++) p3[r] = v[r];
    __syncwarp();
    float2* p2 = sh[sub] + 72 * (q >> 3) + (q & 7);
#pragma unroll
    for (int r = 0; r < 8; r++) v[r] = p2[9 * r];
    dit8<true>(v, wang(-ANG * (float)(q & 7) / 32.0f));
#pragma unroll
    for (int r = 0; r < 8; r++) p2[9 * r] = v[r];
    __syncthreads();
    float2* p1 = sh[sub] + q + (q >> 3);
#pragma unroll
    for (int r = 0; r < 8; r++) v[r] = p1[72 * r];
    dit8<true>(v, wang(-ANG * (float)q / 256.0f));
    const float sc = 1.0f / (512.0f * 512.0f);
    float* o0 = out + ((size_t)n * N + 2 * rp) * N;
    float* o1 = o0 + N;
#pragma unroll
    for (int r = 0; r < 8; r++) {
        int i = q + 64 * r;
        o0[i] = fminf(1.0f, fmaxf(-1.0f, v[r].x * sc));
        o1[i] = fminf(1.0f, fmaxf(-1.0f, v[r].y * sc));
    }
}

// ---------------------------------------------------------------------------
// Streams/events created once at load time (before any capture / checkpoint).
// ---------------------------------------------------------------------------
static cudaStream_t s_chain[NCHAIN];
static cudaEvent_t  s_fork;
static cudaEvent_t  s_join[NCHAIN];
static int s_init = []() {
    for (int i = 0; i < NCHAIN; i++)
        cudaStreamCreateWithFlags(&s_chain[i], cudaStreamNonBlocking);
    cudaEventCreateWithFlags(&s_fork, cudaEventDisableTiming);
    for (int i = 0; i < NCHAIN; i++)
        cudaEventCreateWithFlags(&s_join[i], cudaEventDisableTiming);
    return 0;
}();

extern "C" void kernel_launch(void* const* d_in, const int* in_sizes, int n_in,
                              void* d_out, int out_size) {
    const float* y       = (const float*)d_in[0];
    const float* filters = (const float*)d_in[1];
    float* out = (float*)d_out;

    // Fork capture onto NCHAIN streams; each chain pipelines 16 images
    // through row-fwd -> column-Wiener -> row-inv independently.
    cudaEventRecord(s_fork, 0);
    for (int c = 0; c < NCHAIN; c++)
        cudaStreamWaitEvent(s_chain[c], s_fork, 0);

    for (int c = 0; c < NCHAIN; c++) {
        int n0 = c * IMGS_PER_CHAIN;
        kRowFwdY<<<IMGS_PER_CHAIN * 64, 256, 0, s_chain[c]>>>(y, n0);
        kColHalf<<<IMGS_PER_CHAIN * 66, 256, 0, s_chain[c]>>>(filters, n0);
        kRowInv <<<IMGS_PER_CHAIN * 64, 256, 0, s_chain[c]>>>(out, n0);
        cudaEventRecord(s_join[c], s_chain[c]);
    }
    for (int c = 0; c < NCHAIN; c++)
        cudaStreamWaitEvent(0, s_join[c], 0);
}